// round 12
// baseline (speedup 1.0000x reference)
#include <cuda_runtime.h>
#include <cuda_fp16.h>
#include <math.h>
#include <stdint.h>

// Problem dims
#define DQ    2048
#define RQ    1024
#define MQ    128
#define EQ    64
#define TQ    32768
#define PADA  68

// k3 tiling: 64-token CTA, warp tile 16x64, fp16x3 m16n8k16, 4-stage cp.async
#define KC        16
#define NST       4
#define SAF       24                         // floats per staged A row
#define SBH       24                         // halfs per staged B row
#define A_BYTES   (64 * SAF * 4)             // 6144
#define BH_OFF    A_BYTES
#define BL_OFF    (A_BYTES + 64 * SBH * 2)   // 9216
#define ST_BYTES  (A_BYTES + 2 * 64 * SBH * 2)   // 12288
#define K3_SMEM_BYTES (256 + NST * ST_BYTES)     // 49408

// ---------------- scratch ----------------
__device__ float  g_remb[EQ * RQ];
__device__ float  g_rembT[RQ * EQ];
__device__ float  g_partialT[8][EQ * DQ];   // [e][d] fp32
__device__ __half g_BhT[EQ * DQ];           // fp16-hi of W_combT [e][d]
__device__ __half g_BlT[EQ * DQ];           // fp16-lo
__device__ float  g_biasP[4][EQ];
__device__ float  g_bias[EQ];

__device__ __forceinline__ float mask11(float x) {   // keep 11 significand bits (fp16-exact)
    return __uint_as_float(__float_as_uint(x) & 0xFFFFE000u);
}
__device__ __forceinline__ uint32_t pack_h2(float lo, float hi) {
    __half2 h = __floats2half2_rn(lo, hi);
    return *reinterpret_cast<uint32_t*>(&h);
}
__device__ __forceinline__ uint32_t smem_u32(const void* p) {
    uint32_t a;
    asm("{ .reg .u64 t; cvta.to.shared.u64 t, %1; cvt.u32.u64 %0, t; }" : "=r"(a) : "l"(p));
    return a;
}
__device__ __forceinline__ void cpa16(uint32_t s, const void* g) {
    asm volatile("cp.async.cg.shared.global [%0], [%1], 16;" :: "r"(s), "l"(g));
}
#define CPA_COMMIT() asm volatile("cp.async.commit_group;" ::: "memory")
#define CPA_WAIT2()  asm volatile("cp.async.wait_group 2;" ::: "memory")
#define CPA_WAIT0()  asm volatile("cp.async.wait_group 0;" ::: "memory")

// m16n8k16 fp16 mma, f32 accum, D += A*B (row.col)
__device__ __forceinline__ void mma16(float* d, const uint32_t* a, uint32_t b0, uint32_t b1) {
    asm volatile(
        "mma.sync.aligned.m16n8k16.row.col.f32.f16.f16.f32 "
        "{%0,%1,%2,%3}, {%4,%5,%6,%7}, {%8,%9}, {%0,%1,%2,%3};"
        : "+f"(d[0]), "+f"(d[1]), "+f"(d[2]), "+f"(d[3])
        : "r"(a[0]), "r"(a[1]), "r"(a[2]), "r"(a[3]), "r"(b0), "r"(b1));
}

// ---------------------------------------------------------------------------
// K1: rkhs_emb[e][r] = sum_m emb[e][m]*W_exp[r][m] + b_exp[r], grid (EQ, 4).
// ---------------------------------------------------------------------------
__global__ void k1_remb(const float* __restrict__ W_exp,
                        const float* __restrict__ b_exp,
                        const float* __restrict__ emb,
                        const float* __restrict__ b_hid) {
    __shared__ float4 s_emb[MQ / 4];
    __shared__ float  red[8];
    const int e    = blockIdx.x;
    const int q    = blockIdx.y;
    const int tid  = threadIdx.x;
    const int w    = tid >> 5;
    const int lane = tid & 31;
    if (tid < MQ / 4) s_emb[tid] = reinterpret_cast<const float4*>(emb)[e * (MQ / 4) + tid];
    __syncthreads();
    const float4 ev = s_emb[lane];
    float bacc = 0.f;
#pragma unroll 4
    for (int i = 0; i < 32; i++) {
        const int r = q * 256 + w * 32 + i;
        float4 wv = reinterpret_cast<const float4*>(W_exp)[r * (MQ / 4) + lane];
        float p = wv.x * ev.x + wv.y * ev.y + wv.z * ev.z + wv.w * ev.w;
        p += __shfl_xor_sync(0xffffffffu, p, 16);
        p += __shfl_xor_sync(0xffffffffu, p, 8);
        p += __shfl_xor_sync(0xffffffffu, p, 4);
        p += __shfl_xor_sync(0xffffffffu, p, 2);
        p += __shfl_xor_sync(0xffffffffu, p, 1);
        if (lane == 0) {
            float v = p + b_exp[r];
            g_remb[e * RQ + r]  = v;
            g_rembT[r * EQ + e] = v;
            bacc += b_hid[r] * v;
        }
    }
    if (lane == 0) red[w] = bacc;
    __syncthreads();
    if (tid == 0) {
        float s = 0.f;
#pragma unroll
        for (int i = 0; i < 8; i++) s += red[i];
        g_biasP[q][e] = s;
    }
}

// ---------------------------------------------------------------------------
// K2: split-K GEMM -> partials of W_combT[e][d]
// ---------------------------------------------------------------------------
__global__ __launch_bounds__(256) void k2_part(const float* __restrict__ W_hid) {
    __shared__ float sW[16 * PADA];
    __shared__ float sR[16 * 64];
    const int tid = threadIdx.x;
    const int d0  = blockIdx.x * 64;
    const int r0  = blockIdx.y * 128;
    const int tm  = tid >> 4;
    const int tn  = tid & 15;
    const int rr  = tid >> 4;
    const int dq  = tid & 15;

    float acc[4][4];
#pragma unroll
    for (int i = 0; i < 4; i++)
#pragma unroll
        for (int j = 0; j < 4; j++) acc[i][j] = 0.f;

    const float4* RT4 = reinterpret_cast<const float4*>(g_rembT);

    for (int rk = 0; rk < 128; rk += 16) {
        *reinterpret_cast<float4*>(&sW[rr * PADA + dq * 4]) =
            *reinterpret_cast<const float4*>(&W_hid[(size_t)(r0 + rk + rr) * DQ + d0 + dq * 4]);
        *reinterpret_cast<float4*>(&sR[tid * 4]) = RT4[(size_t)(r0 + rk) * (EQ / 4) + tid];
        __syncthreads();
#pragma unroll
        for (int k = 0; k < 16; k++) {
            float4 a = *reinterpret_cast<const float4*>(&sW[k * PADA + tm * 4]);
            float4 b = *reinterpret_cast<const float4*>(&sR[k * 64 + tn * 4]);
            acc[0][0] += a.x * b.x; acc[0][1] += a.x * b.y; acc[0][2] += a.x * b.z; acc[0][3] += a.x * b.w;
            acc[1][0] += a.y * b.x; acc[1][1] += a.y * b.y; acc[1][2] += a.y * b.z; acc[1][3] += a.y * b.w;
            acc[2][0] += a.z * b.x; acc[2][1] += a.z * b.y; acc[2][2] += a.z * b.z; acc[2][3] += a.z * b.w;
            acc[3][0] += a.w * b.x; acc[3][1] += a.w * b.y; acc[3][2] += a.w * b.z; acc[3][3] += a.w * b.w;
        }
        __syncthreads();
    }
    float* dst = &g_partialT[blockIdx.y][0];
#pragma unroll
    for (int i = 0; i < 4; i++)
#pragma unroll
        for (int j = 0; j < 4; j++)
            dst[(size_t)(tn * 4 + j) * DQ + d0 + tm * 4 + i] = acc[i][j];
}

// K2r: reduce partials -> fp16 hi/lo; block 0 also reduces bias partials.
__global__ void k2_reduce() {
    const int i = blockIdx.x * 256 + threadIdx.x;
    float4 s = make_float4(0.f, 0.f, 0.f, 0.f);
#pragma unroll
    for (int p = 0; p < 8; p++) {
        float4 v = reinterpret_cast<const float4*>(&g_partialT[p][0])[i];
        s.x += v.x; s.y += v.y; s.z += v.z; s.w += v.w;
    }
    float hx = mask11(s.x), hy = mask11(s.y), hz = mask11(s.z), hw = mask11(s.w);
    reinterpret_cast<uint2*>(g_BhT)[i] = make_uint2(pack_h2(hx, hy), pack_h2(hz, hw));
    reinterpret_cast<uint2*>(g_BlT)[i] = make_uint2(pack_h2(s.x - hx, s.y - hy),
                                                   pack_h2(s.z - hz, s.w - hw));
    if (blockIdx.x == 0 && threadIdx.x < EQ) {
        const int e = threadIdx.x;
        g_bias[e] = (g_biasP[0][e] + g_biasP[1][e]) + (g_biasP[2][e] + g_biasP[3][e]);
    }
}

// ---------------------------------------------------------------------------
// K3: fp16x3 mma.sync GEMM [64 tok x 64 exp x 2048] + fused top-2.
// 128 threads (4 warps), warp tile 16x64; 4-stage cp.async ring, 2 in flight.
// ---------------------------------------------------------------------------
__global__ __launch_bounds__(128, 4) void k3_mma(const float* __restrict__ input,
                                                 float* __restrict__ out_idx,
                                                 float* __restrict__ out_w,
                                                 float* __restrict__ aux_ptr) {
    extern __shared__ char smc[];
    float* sbias = reinterpret_cast<float*>(smc);    // [0,64) floats
    char*  stg   = smc + 256;
    const int tid  = threadIdx.x;
    const int w    = tid >> 5;
    const int lane = tid & 31;
    const int g    = lane >> 2;
    const int c    = lane & 3;
    const int tok0 = blockIdx.x * 64;

    if (tid < EQ) sbias[tid] = g_bias[tid];

    float acc[8][4];
#pragma unroll
    for (int j = 0; j < 8; j++)
#pragma unroll
        for (int q2 = 0; q2 < 4; q2++) acc[j][q2] = 0.f;

    // staging coords: A row = tid>>1 (0..63), seg = tid&1 (2 cpa16: cols 8s, 8s+4)
    //                 B expert be = tid>>1, seg bs = tid&1 (1 cpa16 each of Bh, Bl)
    const int arow = tid >> 1, as = tid & 1;
    const int be = tid >> 1, bs = tid & 1;

    const uint32_t stg_u = smem_u32(stg);

    auto issue = [&](int ch, int slot) {
        const uint32_t st = stg_u + slot * ST_BYTES;
        const int k0 = ch * KC;
        const float* ag = input + (size_t)(tok0 + arow) * DQ + k0 + as * 8;
        cpa16(st + arow * (SAF * 4) + as * 32, ag);
        cpa16(st + arow * (SAF * 4) + as * 32 + 16, ag + 4);
        cpa16(st + BH_OFF + be * (SBH * 2) + bs * 16, g_BhT + (size_t)be * DQ + k0 + bs * 8);
        cpa16(st + BL_OFF + be * (SBH * 2) + bs * 16, g_BlT + (size_t)be * DQ + k0 + bs * 8);
    };

    issue(0, 0); CPA_COMMIT();
    issue(1, 1); CPA_COMMIT();
    issue(2, 2); CPA_COMMIT();

    int slot = 0;
    for (int ch = 0; ch < DQ / KC; ch++) {
        CPA_WAIT2();
        __syncthreads();

        const char* st = stg + slot * ST_BYTES;
        const float*  Af = reinterpret_cast<const float*>(st);
        const __half* Bh = reinterpret_cast<const __half*>(st + BH_OFF);
        const __half* Bl = reinterpret_cast<const __half*>(st + BL_OFF);

        // A fragments: LDS.64 fp32 pairs -> split hi/lo in registers
        uint32_t ahf[4], alf[4];
        {
            const int rb = w * 16 + g;
#pragma unroll
            for (int q2 = 0; q2 < 4; q2++) {
                const int row = (q2 & 1) ? rb + 8 : rb;
                const int kk  = 2 * c + ((q2 >> 1) ? 8 : 0);
                float2 v = *reinterpret_cast<const float2*>(&Af[row * SAF + kk]);
                float hx = mask11(v.x), hy = mask11(v.y);
                ahf[q2] = pack_h2(hx, hy);
                alf[q2] = pack_h2(v.x - hx, v.y - hy);
            }
        }

        // pass 1: hi*hi — cache Bh fragments for pass 3
        uint32_t bhf[8][2];
#pragma unroll
        for (int j = 0; j < 8; j++) {
            const int e = j * 8 + g;
            bhf[j][0] = *reinterpret_cast<const uint32_t*>(&Bh[e * SBH + 2 * c]);
            bhf[j][1] = *reinterpret_cast<const uint32_t*>(&Bh[e * SBH + 2 * c + 8]);
            mma16(acc[j], ahf, bhf[j][0], bhf[j][1]);
        }
        // pass 2: hi*lo
#pragma unroll
        for (int j = 0; j < 8; j++) {
            const int e = j * 8 + g;
            uint32_t b0 = *reinterpret_cast<const uint32_t*>(&Bl[e * SBH + 2 * c]);
            uint32_t b1 = *reinterpret_cast<const uint32_t*>(&Bl[e * SBH + 2 * c + 8]);
            mma16(acc[j], ahf, b0, b1);
        }
        // pass 3: lo*hi (reuse cached Bh)
#pragma unroll
        for (int j = 0; j < 8; j++)
            mma16(acc[j], alf, bhf[j][0], bhf[j][1]);

        // prefetch chunk ch+3 into the slot chunk ch-1 used
        if (ch + 3 < DQ / KC) {
            int ns = slot + 3; if (ns >= NST) ns -= NST;
            issue(ch + 3, ns);
        }
        CPA_COMMIT();

        if (++slot == NST) slot = 0;
    }
    CPA_WAIT0();
    __syncthreads();

    // ---- epilogue: logits -> smem [64][65] floats, then top-2 per token ----
    float* slog = reinterpret_cast<float*>(stg);
    {
        const int r0 = w * 16 + g;
#pragma unroll
        for (int j = 0; j < 8; j++) {
            const int col = j * 8 + 2 * c;
            slog[r0 * 65 + col]           = acc[j][0] + sbias[col];
            slog[r0 * 65 + col + 1]       = acc[j][1] + sbias[col + 1];
            slog[(r0 + 8) * 65 + col]     = acc[j][2] + sbias[col];
            slog[(r0 + 8) * 65 + col + 1] = acc[j][3] + sbias[col + 1];
        }
    }
    __syncthreads();

    if (tid < 64) {
        const int t = tid;
        float best = -INFINITY, second = -INFINITY;
        int bi = 0, si = 0;
#pragma unroll 8
        for (int e = 0; e < EQ; e++) {
            float v = slog[t * 65 + e];
            if (v > best)        { second = best; si = bi; best = v; bi = e; }
            else if (v > second) { second = v; si = e; }
        }
        float es  = expf(second - best);
        float inv = 1.f / (1.f + es);
        int gt = tok0 + t;
        out_idx[gt * 2 + 0] = (float)bi;
        out_idx[gt * 2 + 1] = (float)si;
        out_w[gt * 2 + 0]   = inv;
        out_w[gt * 2 + 1]   = es * inv;
    }

    if (blockIdx.x == 0 && tid == 0 && aux_ptr != nullptr) *aux_ptr = 64.0f;
}

// ---------------------------------------------------------------------------
extern "C" void kernel_launch(void* const* d_in, const int* in_sizes, int n_in,
                              void* d_out, int out_size) {
    const float* input = (const float*)d_in[0];
    const float* W_hid = (const float*)d_in[1];
    const float* b_hid = (const float*)d_in[2];
    const float* W_exp = (const float*)d_in[3];
    const float* b_exp = (const float*)d_in[4];
    const float* emb   = (const float*)d_in[5];

    float* out     = (float*)d_out;
    float* out_idx = out;
    float* out_w   = out + 2 * TQ;
    float* aux     = (out_size > 4 * TQ) ? (out + (out_size - 1)) : nullptr;

    cudaFuncSetAttribute(k3_mma, cudaFuncAttributeMaxDynamicSharedMemorySize, K3_SMEM_BYTES);

    k1_remb<<<dim3(EQ, 4), 256>>>(W_exp, b_exp, emb, b_hid);
    k2_part<<<dim3(DQ / 64, 8), 256>>>(W_hid);
    k2_reduce<<<(EQ * DQ / 4) / 256, 256>>>();
    k3_mma<<<TQ / 64, 128, K3_SMEM_BYTES>>>(input, out_idx, out_w, aux);
}

// round 13
// speedup vs baseline: 1.2384x; 1.2384x over previous
#include <cuda_runtime.h>
#include <cuda_fp16.h>
#include <math.h>
#include <stdint.h>

// Problem dims
#define DQ    2048
#define RQ    1024
#define MQ    128
#define EQ    64
#define TQ    32768
#define PADA  68

// k3 tiling: 128-token CTA, warp tile 32x64, fp16x3 m16n8k16, split-K=2,
// 4-stage cp.async ring with 2 chunks in flight.
#define KC        16
#define NST       4
#define KSPLIT    2
#define KHALF     (DQ / KSPLIT)              // 1024
#define SAF       24                         // floats per staged A row
#define SBH       24                         // halfs per staged B row
#define A_BYTES   (128 * SAF * 4)            // 12288
#define BH_OFF    A_BYTES
#define BL_OFF    (A_BYTES + 64 * SBH * 2)   // 15360
#define ST_BYTES  (A_BYTES + 2 * 64 * SBH * 2)   // 18432
#define K3_SMEM_BYTES (256 + NST * ST_BYTES)     // 73984

// ---------------- scratch ----------------
__device__ float  g_remb[EQ * RQ];
__device__ float  g_rembT[RQ * EQ];
__device__ float  g_partialT[8][EQ * DQ];   // [e][d] fp32
__device__ __half g_BhT[EQ * DQ];           // fp16-hi of W_combT [e][d]
__device__ __half g_BlT[EQ * DQ];           // fp16-lo
__device__ float  g_biasP[4][EQ];
__device__ float  g_bias[EQ];
__device__ float  g_plog[KSPLIT * TQ * EQ]; // split-K partial logits (16.8 MB)

__device__ __forceinline__ float mask11(float x) {   // keep 11 significand bits (fp16-exact)
    return __uint_as_float(__float_as_uint(x) & 0xFFFFE000u);
}
__device__ __forceinline__ uint32_t pack_h2(float lo, float hi) {
    __half2 h = __floats2half2_rn(lo, hi);
    return *reinterpret_cast<uint32_t*>(&h);
}
__device__ __forceinline__ uint32_t smem_u32(const void* p) {
    uint32_t a;
    asm("{ .reg .u64 t; cvta.to.shared.u64 t, %1; cvt.u32.u64 %0, t; }" : "=r"(a) : "l"(p));
    return a;
}
__device__ __forceinline__ void cpa16(uint32_t s, const void* g) {
    asm volatile("cp.async.cg.shared.global [%0], [%1], 16;" :: "r"(s), "l"(g));
}
#define CPA_COMMIT() asm volatile("cp.async.commit_group;" ::: "memory")
#define CPA_WAIT2()  asm volatile("cp.async.wait_group 2;" ::: "memory")
#define CPA_WAIT0()  asm volatile("cp.async.wait_group 0;" ::: "memory")

// m16n8k16 fp16 mma, f32 accum, D += A*B (row.col)
__device__ __forceinline__ void mma16(float* d, const uint32_t* a, uint32_t b0, uint32_t b1) {
    asm volatile(
        "mma.sync.aligned.m16n8k16.row.col.f32.f16.f16.f32 "
        "{%0,%1,%2,%3}, {%4,%5,%6,%7}, {%8,%9}, {%0,%1,%2,%3};"
        : "+f"(d[0]), "+f"(d[1]), "+f"(d[2]), "+f"(d[3])
        : "r"(a[0]), "r"(a[1]), "r"(a[2]), "r"(a[3]), "r"(b0), "r"(b1));
}

// ---------------------------------------------------------------------------
// K1: rkhs_emb[e][r] = sum_m emb[e][m]*W_exp[r][m] + b_exp[r], grid (EQ, 4).
// ---------------------------------------------------------------------------
__global__ void k1_remb(const float* __restrict__ W_exp,
                        const float* __restrict__ b_exp,
                        const float* __restrict__ emb,
                        const float* __restrict__ b_hid) {
    __shared__ float4 s_emb[MQ / 4];
    __shared__ float  red[8];
    const int e    = blockIdx.x;
    const int q    = blockIdx.y;
    const int tid  = threadIdx.x;
    const int w    = tid >> 5;
    const int lane = tid & 31;
    if (tid < MQ / 4) s_emb[tid] = reinterpret_cast<const float4*>(emb)[e * (MQ / 4) + tid];
    __syncthreads();
    const float4 ev = s_emb[lane];
    float bacc = 0.f;
#pragma unroll 4
    for (int i = 0; i < 32; i++) {
        const int r = q * 256 + w * 32 + i;
        float4 wv = reinterpret_cast<const float4*>(W_exp)[r * (MQ / 4) + lane];
        float p = wv.x * ev.x + wv.y * ev.y + wv.z * ev.z + wv.w * ev.w;
        p += __shfl_xor_sync(0xffffffffu, p, 16);
        p += __shfl_xor_sync(0xffffffffu, p, 8);
        p += __shfl_xor_sync(0xffffffffu, p, 4);
        p += __shfl_xor_sync(0xffffffffu, p, 2);
        p += __shfl_xor_sync(0xffffffffu, p, 1);
        if (lane == 0) {
            float v = p + b_exp[r];
            g_remb[e * RQ + r]  = v;
            g_rembT[r * EQ + e] = v;
            bacc += b_hid[r] * v;
        }
    }
    if (lane == 0) red[w] = bacc;
    __syncthreads();
    if (tid == 0) {
        float s = 0.f;
#pragma unroll
        for (int i = 0; i < 8; i++) s += red[i];
        g_biasP[q][e] = s;
    }
}

// ---------------------------------------------------------------------------
// K2: split-K GEMM -> partials of W_combT[e][d]
// ---------------------------------------------------------------------------
__global__ __launch_bounds__(256) void k2_part(const float* __restrict__ W_hid) {
    __shared__ float sW[16 * PADA];
    __shared__ float sR[16 * 64];
    const int tid = threadIdx.x;
    const int d0  = blockIdx.x * 64;
    const int r0  = blockIdx.y * 128;
    const int tm  = tid >> 4;
    const int tn  = tid & 15;
    const int rr  = tid >> 4;
    const int dq  = tid & 15;

    float acc[4][4];
#pragma unroll
    for (int i = 0; i < 4; i++)
#pragma unroll
        for (int j = 0; j < 4; j++) acc[i][j] = 0.f;

    const float4* RT4 = reinterpret_cast<const float4*>(g_rembT);

    for (int rk = 0; rk < 128; rk += 16) {
        *reinterpret_cast<float4*>(&sW[rr * PADA + dq * 4]) =
            *reinterpret_cast<const float4*>(&W_hid[(size_t)(r0 + rk + rr) * DQ + d0 + dq * 4]);
        *reinterpret_cast<float4*>(&sR[tid * 4]) = RT4[(size_t)(r0 + rk) * (EQ / 4) + tid];
        __syncthreads();
#pragma unroll
        for (int k = 0; k < 16; k++) {
            float4 a = *reinterpret_cast<const float4*>(&sW[k * PADA + tm * 4]);
            float4 b = *reinterpret_cast<const float4*>(&sR[k * 64 + tn * 4]);
            acc[0][0] += a.x * b.x; acc[0][1] += a.x * b.y; acc[0][2] += a.x * b.z; acc[0][3] += a.x * b.w;
            acc[1][0] += a.y * b.x; acc[1][1] += a.y * b.y; acc[1][2] += a.y * b.z; acc[1][3] += a.y * b.w;
            acc[2][0] += a.z * b.x; acc[2][1] += a.z * b.y; acc[2][2] += a.z * b.z; acc[2][3] += a.z * b.w;
            acc[3][0] += a.w * b.x; acc[3][1] += a.w * b.y; acc[3][2] += a.w * b.z; acc[3][3] += a.w * b.w;
        }
        __syncthreads();
    }
    float* dst = &g_partialT[blockIdx.y][0];
#pragma unroll
    for (int i = 0; i < 4; i++)
#pragma unroll
        for (int j = 0; j < 4; j++)
            dst[(size_t)(tn * 4 + j) * DQ + d0 + tm * 4 + i] = acc[i][j];
}

// K2r: reduce partials -> fp16 hi/lo; block 0 also reduces bias partials.
__global__ void k2_reduce() {
    const int i = blockIdx.x * 256 + threadIdx.x;
    float4 s = make_float4(0.f, 0.f, 0.f, 0.f);
#pragma unroll
    for (int p = 0; p < 8; p++) {
        float4 v = reinterpret_cast<const float4*>(&g_partialT[p][0])[i];
        s.x += v.x; s.y += v.y; s.z += v.z; s.w += v.w;
    }
    float hx = mask11(s.x), hy = mask11(s.y), hz = mask11(s.z), hw = mask11(s.w);
    reinterpret_cast<uint2*>(g_BhT)[i] = make_uint2(pack_h2(hx, hy), pack_h2(hz, hw));
    reinterpret_cast<uint2*>(g_BlT)[i] = make_uint2(pack_h2(s.x - hx, s.y - hy),
                                                   pack_h2(s.z - hz, s.w - hw));
    if (blockIdx.x == 0 && threadIdx.x < EQ) {
        const int e = threadIdx.x;
        g_bias[e] = (g_biasP[0][e] + g_biasP[1][e]) + (g_biasP[2][e] + g_biasP[3][e]);
    }
}

// ---------------------------------------------------------------------------
// K3a: fp16x3 mma.sync GEMM partials. CTA = 128 tok x 64 exp x K-half.
// grid (TQ/128, 2); blockIdx.y selects K half. Raw fp32 partials -> g_plog.
// ---------------------------------------------------------------------------
__global__ __launch_bounds__(128, 3) void k3_mma(const float* __restrict__ input) {
    extern __shared__ char smc[];
    char* stg = smc + 256;
    const int tid  = threadIdx.x;
    const int w    = tid >> 5;
    const int lane = tid & 31;
    const int g    = lane >> 2;
    const int c    = lane & 3;
    const int tok0 = blockIdx.x * 128;
    const int ks   = blockIdx.y;
    const int kb   = ks * KHALF;

    float acc[2][8][4];
#pragma unroll
    for (int i = 0; i < 2; i++)
#pragma unroll
        for (int j = 0; j < 8; j++)
#pragma unroll
            for (int q2 = 0; q2 < 4; q2++) acc[i][j][q2] = 0.f;

    // staging coords
    const int arow = tid >> 2, aj = tid & 3;   // A: rows arow+32u, 16B col aj
    const int be = tid >> 1, bs = tid & 1;     // B: expert be, 16B seg bs

    const uint32_t stg_u = smem_u32(stg);

    auto issue = [&](int ch, int slot) {
        const uint32_t st = stg_u + slot * ST_BYTES;
        const int k0 = kb + ch * KC;
#pragma unroll
        for (int u = 0; u < 4; u++) {
            int row = arow + 32 * u;
            cpa16(st + row * (SAF * 4) + aj * 16,
                  input + (size_t)(tok0 + row) * DQ + k0 + aj * 4);
        }
        cpa16(st + BH_OFF + be * (SBH * 2) + bs * 16, g_BhT + (size_t)be * DQ + k0 + bs * 8);
        cpa16(st + BL_OFF + be * (SBH * 2) + bs * 16, g_BlT + (size_t)be * DQ + k0 + bs * 8);
    };

    issue(0, 0); CPA_COMMIT();
    issue(1, 1); CPA_COMMIT();
    issue(2, 2); CPA_COMMIT();

    int slot = 0;
    for (int ch = 0; ch < KHALF / KC; ch++) {
        CPA_WAIT2();
        __syncthreads();

        const char* st = stg + slot * ST_BYTES;
        const float*  Af = reinterpret_cast<const float*>(st);
        const __half* Bh = reinterpret_cast<const __half*>(st + BH_OFF);
        const __half* Bl = reinterpret_cast<const __half*>(st + BL_OFF);

        // A fragments: LDS.64 fp32 pairs -> split hi/lo in registers
        uint32_t ahf[2][4], alf[2][4];
#pragma unroll
        for (int i = 0; i < 2; i++) {
            const int rb = w * 32 + i * 16 + g;
#pragma unroll
            for (int q2 = 0; q2 < 4; q2++) {
                const int row = (q2 & 1) ? rb + 8 : rb;
                const int kk  = 2 * c + ((q2 >> 1) ? 8 : 0);
                float2 v = *reinterpret_cast<const float2*>(&Af[row * SAF + kk]);
                float hx = mask11(v.x), hy = mask11(v.y);
                ahf[i][q2] = pack_h2(hx, hy);
                alf[i][q2] = pack_h2(v.x - hx, v.y - hy);
            }
        }

        // pass 1: hi*hi — cache Bh fragments for pass 3
        uint32_t bhf[8][2];
#pragma unroll
        for (int j = 0; j < 8; j++) {
            const int e = j * 8 + g;
            bhf[j][0] = *reinterpret_cast<const uint32_t*>(&Bh[e * SBH + 2 * c]);
            bhf[j][1] = *reinterpret_cast<const uint32_t*>(&Bh[e * SBH + 2 * c + 8]);
            mma16(acc[0][j], ahf[0], bhf[j][0], bhf[j][1]);
            mma16(acc[1][j], ahf[1], bhf[j][0], bhf[j][1]);
        }
        // pass 2: hi*lo
#pragma unroll
        for (int j = 0; j < 8; j++) {
            const int e = j * 8 + g;
            uint32_t b0 = *reinterpret_cast<const uint32_t*>(&Bl[e * SBH + 2 * c]);
            uint32_t b1 = *reinterpret_cast<const uint32_t*>(&Bl[e * SBH + 2 * c + 8]);
            mma16(acc[0][j], ahf[0], b0, b1);
            mma16(acc[1][j], ahf[1], b0, b1);
        }
        // pass 3: lo*hi (reuse cached Bh)
#pragma unroll
        for (int j = 0; j < 8; j++) {
            mma16(acc[0][j], alf[0], bhf[j][0], bhf[j][1]);
            mma16(acc[1][j], alf[1], bhf[j][0], bhf[j][1]);
        }

        if (ch + 3 < KHALF / KC) {
            int ns = slot + 3; if (ns >= NST) ns -= NST;
            issue(ch + 3, ns);
        }
        CPA_COMMIT();

        if (++slot == NST) slot = 0;
    }
    CPA_WAIT0();

    // ---- epilogue: raw fp32 partials -> g_plog[ks][tok][e] via STG.64 ----
    float* dst = g_plog + (size_t)ks * TQ * EQ;
#pragma unroll
    for (int i = 0; i < 2; i++) {
        const int r0 = tok0 + w * 32 + i * 16 + g;
#pragma unroll
        for (int j = 0; j < 8; j++) {
            const int col = j * 8 + 2 * c;
            *reinterpret_cast<float2*>(&dst[(size_t)r0 * EQ + col]) =
                make_float2(acc[i][j][0], acc[i][j][1]);
            *reinterpret_cast<float2*>(&dst[(size_t)(r0 + 8) * EQ + col]) =
                make_float2(acc[i][j][2], acc[i][j][3]);
        }
    }
}

// ---------------------------------------------------------------------------
// K3r: sum the two K-half partials + bias, top-2 + renormalized softmax.
// 128 threads/block, one token per thread; partials are L2-resident.
// ---------------------------------------------------------------------------
__global__ __launch_bounds__(128) void k3_red(float* __restrict__ out_idx,
                                              float* __restrict__ out_w,
                                              float* __restrict__ aux_ptr) {
    __shared__ float sb[EQ];
    const int tid = threadIdx.x;
    const int t   = blockIdx.x * 128 + tid;
    if (tid < EQ) sb[tid] = g_bias[tid];
    __syncthreads();

    const float4* p0 = reinterpret_cast<const float4*>(g_plog + (size_t)t * EQ);
    const float4* p1 = reinterpret_cast<const float4*>(g_plog + (size_t)(TQ + t) * EQ);

    float best = -INFINITY, second = -INFINITY;
    int bi = 0, si = 0;
#pragma unroll
    for (int i = 0; i < EQ / 4; i++) {
        float4 a = p0[i];
        float4 b = p1[i];
        float v[4];
        v[0] = a.x + b.x + sb[4 * i + 0];
        v[1] = a.y + b.y + sb[4 * i + 1];
        v[2] = a.z + b.z + sb[4 * i + 2];
        v[3] = a.w + b.w + sb[4 * i + 3];
#pragma unroll
        for (int q = 0; q < 4; q++) {
            const int e = 4 * i + q;
            if (v[q] > best)        { second = best; si = bi; best = v[q]; bi = e; }
            else if (v[q] > second) { second = v[q]; si = e; }
        }
    }
    float es  = expf(second - best);
    float inv = 1.f / (1.f + es);
    out_idx[t * 2 + 0] = (float)bi;
    out_idx[t * 2 + 1] = (float)si;
    out_w[t * 2 + 0]   = inv;
    out_w[t * 2 + 1]   = es * inv;

    if (blockIdx.x == 0 && tid == 0 && aux_ptr != nullptr) *aux_ptr = 64.0f;
}

// ---------------------------------------------------------------------------
extern "C" void kernel_launch(void* const* d_in, const int* in_sizes, int n_in,
                              void* d_out, int out_size) {
    const float* input = (const float*)d_in[0];
    const float* W_hid = (const float*)d_in[1];
    const float* b_hid = (const float*)d_in[2];
    const float* W_exp = (const float*)d_in[3];
    const float* b_exp = (const float*)d_in[4];
    const float* emb   = (const float*)d_in[5];

    float* out     = (float*)d_out;
    float* out_idx = out;
    float* out_w   = out + 2 * TQ;
    float* aux     = (out_size > 4 * TQ) ? (out + (out_size - 1)) : nullptr;

    cudaFuncSetAttribute(k3_mma, cudaFuncAttributeMaxDynamicSharedMemorySize, K3_SMEM_BYTES);

    k1_remb<<<dim3(EQ, 4), 256>>>(W_exp, b_exp, emb, b_hid);
    k2_part<<<dim3(DQ / 64, 8), 256>>>(W_hid);
    k2_reduce<<<(EQ * DQ / 4) / 256, 256>>>();
    k3_mma<<<dim3(TQ / 128, KSPLIT), 128, K3_SMEM_BYTES>>>(input);
    k3_red<<<TQ / 128, 128>>>(out_idx, out_w, aux);
}

// round 15
// speedup vs baseline: 1.2537x; 1.0124x over previous
#include <cuda_runtime.h>
#include <cuda_fp16.h>
#include <math.h>
#include <stdint.h>

// Problem dims
#define DQ    2048
#define RQ    1024
#define MQ    128
#define EQ    64
#define TQ    32768
#define PADA  68

// k3 tiling: 128-token CTA, warp tile 32x64, fp16x3 m16n8k16, split-K=2,
// 3-stage cp.async ring (1 chunk prefetch depth) -> 55.5 KB smem, 4 CTAs/SM.
#define KC        16
#define NST       3
#define KSPLIT    2
#define KHALF     (DQ / KSPLIT)              // 1024
#define SAF       24                         // floats per staged A row
#define SBH       24                         // halfs per staged B row
#define A_BYTES   (128 * SAF * 4)            // 12288
#define BH_OFF    A_BYTES
#define BL_OFF    (A_BYTES + 64 * SBH * 2)   // 15360
#define ST_BYTES  (A_BYTES + 2 * 64 * SBH * 2)   // 18432
#define K3_SMEM_BYTES (256 + NST * ST_BYTES)     // 55552

// ---------------- scratch ----------------
__device__ float  g_remb[EQ * RQ];
__device__ float  g_rembT[RQ * EQ];
__device__ float  g_partialT[8][EQ * DQ];   // [e][d] fp32
__device__ __half g_BhT[EQ * DQ];           // fp16-hi of W_combT [e][d]
__device__ __half g_BlT[EQ * DQ];           // fp16-lo
__device__ float  g_biasP[4][EQ];
__device__ float  g_bias[EQ];
__device__ float  g_plog[KSPLIT * TQ * EQ]; // split-K partial logits (16.8 MB)

__device__ __forceinline__ float mask11(float x) {   // keep 11 significand bits (fp16-exact)
    return __uint_as_float(__float_as_uint(x) & 0xFFFFE000u);
}
__device__ __forceinline__ uint32_t pack_h2(float lo, float hi) {
    __half2 h = __floats2half2_rn(lo, hi);
    return *reinterpret_cast<uint32_t*>(&h);
}
__device__ __forceinline__ uint32_t smem_u32(const void* p) {
    uint32_t a;
    asm("{ .reg .u64 t; cvta.to.shared.u64 t, %1; cvt.u32.u64 %0, t; }" : "=r"(a) : "l"(p));
    return a;
}
__device__ __forceinline__ void cpa16(uint32_t s, const void* g) {
    asm volatile("cp.async.cg.shared.global [%0], [%1], 16;" :: "r"(s), "l"(g));
}
#define CPA_COMMIT() asm volatile("cp.async.commit_group;" ::: "memory")
#define CPA_WAIT1()  asm volatile("cp.async.wait_group 1;" ::: "memory")
#define CPA_WAIT0()  asm volatile("cp.async.wait_group 0;" ::: "memory")

// m16n8k16 fp16 mma, f32 accum, D += A*B (row.col)
__device__ __forceinline__ void mma16(float* d, const uint32_t* a, uint32_t b0, uint32_t b1) {
    asm volatile(
        "mma.sync.aligned.m16n8k16.row.col.f32.f16.f16.f32 "
        "{%0,%1,%2,%3}, {%4,%5,%6,%7}, {%8,%9}, {%0,%1,%2,%3};"
        : "+f"(d[0]), "+f"(d[1]), "+f"(d[2]), "+f"(d[3])
        : "r"(a[0]), "r"(a[1]), "r"(a[2]), "r"(a[3]), "r"(b0), "r"(b1));
}

// ---------------------------------------------------------------------------
// K1: rkhs_emb[e][r] = sum_m emb[e][m]*W_exp[r][m] + b_exp[r], grid (EQ, 4).
// ---------------------------------------------------------------------------
__global__ void k1_remb(const float* __restrict__ W_exp,
                        const float* __restrict__ b_exp,
                        const float* __restrict__ emb,
                        const float* __restrict__ b_hid) {
    __shared__ float4 s_emb[MQ / 4];
    __shared__ float  red[8];
    const int e    = blockIdx.x;
    const int q    = blockIdx.y;
    const int tid  = threadIdx.x;
    const int w    = tid >> 5;
    const int lane = tid & 31;
    if (tid < MQ / 4) s_emb[tid] = reinterpret_cast<const float4*>(emb)[e * (MQ / 4) + tid];
    __syncthreads();
    const float4 ev = s_emb[lane];
    float bacc = 0.f;
#pragma unroll 4
    for (int i = 0; i < 32; i++) {
        const int r = q * 256 + w * 32 + i;
        float4 wv = reinterpret_cast<const float4*>(W_exp)[r * (MQ / 4) + lane];
        float p = wv.x * ev.x + wv.y * ev.y + wv.z * ev.z + wv.w * ev.w;
        p += __shfl_xor_sync(0xffffffffu, p, 16);
        p += __shfl_xor_sync(0xffffffffu, p, 8);
        p += __shfl_xor_sync(0xffffffffu, p, 4);
        p += __shfl_xor_sync(0xffffffffu, p, 2);
        p += __shfl_xor_sync(0xffffffffu, p, 1);
        if (lane == 0) {
            float v = p + b_exp[r];
            g_remb[e * RQ + r]  = v;
            g_rembT[r * EQ + e] = v;
            bacc += b_hid[r] * v;
        }
    }
    if (lane == 0) red[w] = bacc;
    __syncthreads();
    if (tid == 0) {
        float s = 0.f;
#pragma unroll
        for (int i = 0; i < 8; i++) s += red[i];
        g_biasP[q][e] = s;
    }
}

// ---------------------------------------------------------------------------
// K2: split-K GEMM -> partials of W_combT[e][d]
// ---------------------------------------------------------------------------
__global__ __launch_bounds__(256) void k2_part(const float* __restrict__ W_hid) {
    __shared__ float sW[16 * PADA];
    __shared__ float sR[16 * 64];
    const int tid = threadIdx.x;
    const int d0  = blockIdx.x * 64;
    const int r0  = blockIdx.y * 128;
    const int tm  = tid >> 4;
    const int tn  = tid & 15;
    const int rr  = tid >> 4;
    const int dq  = tid & 15;

    float acc[4][4];
#pragma unroll
    for (int i = 0; i < 4; i++)
#pragma unroll
        for (int j = 0; j < 4; j++) acc[i][j] = 0.f;

    const float4* RT4 = reinterpret_cast<const float4*>(g_rembT);

    for (int rk = 0; rk < 128; rk += 16) {
        *reinterpret_cast<float4*>(&sW[rr * PADA + dq * 4]) =
            *reinterpret_cast<const float4*>(&W_hid[(size_t)(r0 + rk + rr) * DQ + d0 + dq * 4]);
        *reinterpret_cast<float4*>(&sR[tid * 4]) = RT4[(size_t)(r0 + rk) * (EQ / 4) + tid];
        __syncthreads();
#pragma unroll
        for (int k = 0; k < 16; k++) {
            float4 a = *reinterpret_cast<const float4*>(&sW[k * PADA + tm * 4]);
            float4 b = *reinterpret_cast<const float4*>(&sR[k * 64 + tn * 4]);
            acc[0][0] += a.x * b.x; acc[0][1] += a.x * b.y; acc[0][2] += a.x * b.z; acc[0][3] += a.x * b.w;
            acc[1][0] += a.y * b.x; acc[1][1] += a.y * b.y; acc[1][2] += a.y * b.z; acc[1][3] += a.y * b.w;
            acc[2][0] += a.z * b.x; acc[2][1] += a.z * b.y; acc[2][2] += a.z * b.z; acc[2][3] += a.z * b.w;
            acc[3][0] += a.w * b.x; acc[3][1] += a.w * b.y; acc[3][2] += a.w * b.z; acc[3][3] += a.w * b.w;
        }
        __syncthreads();
    }
    float* dst = &g_partialT[blockIdx.y][0];
#pragma unroll
    for (int i = 0; i < 4; i++)
#pragma unroll
        for (int j = 0; j < 4; j++)
            dst[(size_t)(tn * 4 + j) * DQ + d0 + tm * 4 + i] = acc[i][j];
}

// K2r: reduce partials -> fp16 hi/lo; block 0 also reduces bias partials.
__global__ void k2_reduce() {
    const int i = blockIdx.x * 256 + threadIdx.x;
    float4 s = make_float4(0.f, 0.f, 0.f, 0.f);
#pragma unroll
    for (int p = 0; p < 8; p++) {
        float4 v = reinterpret_cast<const float4*>(&g_partialT[p][0])[i];
        s.x += v.x; s.y += v.y; s.z += v.z; s.w += v.w;
    }
    float hx = mask11(s.x), hy = mask11(s.y), hz = mask11(s.z), hw = mask11(s.w);
    reinterpret_cast<uint2*>(g_BhT)[i] = make_uint2(pack_h2(hx, hy), pack_h2(hz, hw));
    reinterpret_cast<uint2*>(g_BlT)[i] = make_uint2(pack_h2(s.x - hx, s.y - hy),
                                                   pack_h2(s.z - hz, s.w - hw));
    if (blockIdx.x == 0 && threadIdx.x < EQ) {
        const int e = threadIdx.x;
        g_bias[e] = (g_biasP[0][e] + g_biasP[1][e]) + (g_biasP[2][e] + g_biasP[3][e]);
    }
}

// ---------------------------------------------------------------------------
// K3a: fp16x3 mma.sync GEMM partials. CTA = 128 tok x 64 exp x K-half.
// grid (TQ/128, 2); blockIdx.y selects K half. Raw fp32 partials -> g_plog.
// 3-stage ring, wait_group 1; 4 CTAs/SM -> whole grid in one wave.
// ---------------------------------------------------------------------------
__global__ __launch_bounds__(128, 4) void k3_mma(const float* __restrict__ input) {
    extern __shared__ char smc[];
    char* stg = smc + 256;
    const int tid  = threadIdx.x;
    const int w    = tid >> 5;
    const int lane = tid & 31;
    const int g    = lane >> 2;
    const int c    = lane & 3;
    const int tok0 = blockIdx.x * 128;
    const int ks   = blockIdx.y;
    const int kb   = ks * KHALF;

    float acc[2][8][4];
#pragma unroll
    for (int i = 0; i < 2; i++)
#pragma unroll
        for (int j = 0; j < 8; j++)
#pragma unroll
            for (int q2 = 0; q2 < 4; q2++) acc[i][j][q2] = 0.f;

    // staging coords
    const int arow = tid >> 2, aj = tid & 3;   // A: rows arow+32u, 16B col aj
    const int be = tid >> 1, bs = tid & 1;     // B: expert be, 16B seg bs

    const uint32_t stg_u = smem_u32(stg);

    auto issue = [&](int ch, int slot) {
        const uint32_t st = stg_u + slot * ST_BYTES;
        const int k0 = kb + ch * KC;
#pragma unroll
        for (int u = 0; u < 4; u++) {
            int row = arow + 32 * u;
            cpa16(st + row * (SAF * 4) + aj * 16,
                  input + (size_t)(tok0 + row) * DQ + k0 + aj * 4);
        }
        cpa16(st + BH_OFF + be * (SBH * 2) + bs * 16, g_BhT + (size_t)be * DQ + k0 + bs * 8);
        cpa16(st + BL_OFF + be * (SBH * 2) + bs * 16, g_BlT + (size_t)be * DQ + k0 + bs * 8);
    };

    issue(0, 0); CPA_COMMIT();
    issue(1, 1); CPA_COMMIT();

    int slot = 0;
    for (int ch = 0; ch < KHALF / KC; ch++) {
        CPA_WAIT1();
        __syncthreads();

        const char* st = stg + slot * ST_BYTES;
        const float*  Af = reinterpret_cast<const float*>(st);
        const __half* Bh = reinterpret_cast<const __half*>(st + BH_OFF);
        const __half* Bl = reinterpret_cast<const __half*>(st + BL_OFF);

        // A fragments: LDS.64 fp32 pairs -> split hi/lo in registers
        uint32_t ahf[2][4], alf[2][4];
#pragma unroll
        for (int i = 0; i < 2; i++) {
            const int rb = w * 32 + i * 16 + g;
#pragma unroll
            for (int q2 = 0; q2 < 4; q2++) {
                const int row = (q2 & 1) ? rb + 8 : rb;
                const int kk  = 2 * c + ((q2 >> 1) ? 8 : 0);
                float2 v = *reinterpret_cast<const float2*>(&Af[row * SAF + kk]);
                float hx = mask11(v.x), hy = mask11(v.y);
                ahf[i][q2] = pack_h2(hx, hy);
                alf[i][q2] = pack_h2(v.x - hx, v.y - hy);
            }
        }

        // pass 1: hi*hi — cache Bh fragments for pass 3
        uint32_t bhf[8][2];
#pragma unroll
        for (int j = 0; j < 8; j++) {
            const int e = j * 8 + g;
            bhf[j][0] = *reinterpret_cast<const uint32_t*>(&Bh[e * SBH + 2 * c]);
            bhf[j][1] = *reinterpret_cast<const uint32_t*>(&Bh[e * SBH + 2 * c + 8]);
            mma16(acc[0][j], ahf[0], bhf[j][0], bhf[j][1]);
            mma16(acc[1][j], ahf[1], bhf[j][0], bhf[j][1]);
        }
        // pass 2: hi*lo
#pragma unroll
        for (int j = 0; j < 8; j++) {
            const int e = j * 8 + g;
            uint32_t b0 = *reinterpret_cast<const uint32_t*>(&Bl[e * SBH + 2 * c]);
            uint32_t b1 = *reinterpret_cast<const uint32_t*>(&Bl[e * SBH + 2 * c + 8]);
            mma16(acc[0][j], ahf[0], b0, b1);
            mma16(acc[1][j], ahf[1], b0, b1);
        }
        // pass 3: lo*hi (reuse cached Bh)
#pragma unroll
        for (int j = 0; j < 8; j++) {
            mma16(acc[0][j], alf[0], bhf[j][0], bhf[j][1]);
            mma16(acc[1][j], alf[1], bhf[j][0], bhf[j][1]);
        }

        // prefetch chunk ch+2 into the slot chunk ch-1 used (sync above
        // guarantees all warps are past chunk ch-1's compute)
        if (ch + 2 < KHALF / KC) {
            int ns = slot + 2; if (ns >= NST) ns -= NST;
            issue(ch + 2, ns);
        }
        CPA_COMMIT();

        if (++slot == NST) slot = 0;
    }
    CPA_WAIT0();

    // ---- epilogue: raw fp32 partials -> g_plog[ks][tok][e] via STG.64 ----
    float* dst = g_plog + (size_t)ks * TQ * EQ;
#pragma unroll
    for (int i = 0; i < 2; i++) {
        const int r0 = tok0 + w * 32 + i * 16 + g;
#pragma unroll
        for (int j = 0; j < 8; j++) {
            const int col = j * 8 + 2 * c;
            *reinterpret_cast<float2*>(&dst[(size_t)r0 * EQ + col]) =
                make_float2(acc[i][j][0], acc[i][j][1]);
            *reinterpret_cast<float2*>(&dst[(size_t)(r0 + 8) * EQ + col]) =
                make_float2(acc[i][j][2], acc[i][j][3]);
        }
    }
}

// ---------------------------------------------------------------------------
// K3r: sum the two K-half partials + bias, top-2 + renormalized softmax.
// ---------------------------------------------------------------------------
__global__ __launch_bounds__(128) void k3_red(float* __restrict__ out_idx,
                                              float* __restrict__ out_w,
                                              float* __restrict__ aux_ptr) {
    __shared__ float sb[EQ];
    const int tid = threadIdx.x;
    const int t   = blockIdx.x * 128 + tid;
    if (tid < EQ) sb[tid] = g_bias[tid];
    __syncthreads();

    const float4* p0 = reinterpret_cast<const float4*>(g_plog + (size_t)t * EQ);
    const float4* p1 = reinterpret_cast<const float4*>(g_plog + (size_t)(TQ + t) * EQ);

    float best = -INFINITY, second = -INFINITY;
    int bi = 0, si = 0;
#pragma unroll
    for (int i = 0; i < EQ / 4; i++) {
        float4 a = p0[i];
        float4 b = p1[i];
        float v[4];
        v[0] = a.x + b.x + sb[4 * i + 0];
        v[1] = a.y + b.y + sb[4 * i + 1];
        v[2] = a.z + b.z + sb[4 * i + 2];
        v[3] = a.w + b.w + sb[4 * i + 3];
#pragma unroll
        for (int q = 0; q < 4; q++) {
            const int e = 4 * i + q;
            if (v[q] > best)        { second = best; si = bi; best = v[q]; bi = e; }
            else if (v[q] > second) { second = v[q]; si = e; }
        }
    }
    float es  = expf(second - best);
    float inv = 1.f / (1.f + es);
    out_idx[t * 2 + 0] = (float)bi;
    out_idx[t * 2 + 1] = (float)si;
    out_w[t * 2 + 0]   = inv;
    out_w[t * 2 + 1]   = es * inv;

    if (blockIdx.x == 0 && tid == 0 && aux_ptr != nullptr) *aux_ptr = 64.0f;
}

// ---------------------------------------------------------------------------
extern "C" void kernel_launch(void* const* d_in, const int* in_sizes, int n_in,
                              void* d_out, int out_size) {
    const float* input = (const float*)d_in[0];
    const float* W_hid = (const float*)d_in[1];
    const float* b_hid = (const float*)d_in[2];
    const float* W_exp = (const float*)d_in[3];
    const float* b_exp = (const float*)d_in[4];
    const float* emb   = (const float*)d_in[5];

    float* out     = (float*)d_out;
    float* out_idx = out;
    float* out_w   = out + 2 * TQ;
    float* aux     = (out_size > 4 * TQ) ? (out + (out_size - 1)) : nullptr;

    cudaFuncSetAttribute(k3_mma, cudaFuncAttributeMaxDynamicSharedMemorySize, K3_SMEM_BYTES);

    k1_remb<<<dim3(EQ, 4), 256>>>(W_exp, b_exp, emb, b_hid);
    k2_part<<<dim3(DQ / 64, 8), 256>>>(W_hid);
    k2_reduce<<<(EQ * DQ / 4) / 256, 256>>>();
    k3_mma<<<dim3(TQ / 128, KSPLIT), 128, K3_SMEM_BYTES>>>(input);
    k3_red<<<TQ / 128, 128>>>(out_idx, out_w, aux);
}